// round 14
// baseline (speedup 1.0000x reference)
#include <cuda_runtime.h>
#include <cuda_bf16.h>

// FINAL kernel — converged optimum (87.87–88.22us across 7 runs, sigma
// ~0.13us; DRAM-roofline-bound at ~6.37 TB/s combined r+w, ~80% of HBM3e
// spec for a balanced 1:1 streaming mix).
//
// Output layout (flattened f32 concat of the reference tuple):
//   [0, 3V)                      verts_3d   (V x 3)
//   [3V, 3V + Fe)                faces cast to f32 (Fe = in_sizes[3])
//   [3V + Fe, 3V + Fe + V*D)     verts_features copy
//
// One fused kernel over a flat interleaved work-item space:
//   items [0, Wfeat)           : features copy, 4 floats/item (float4)
//   items [Wfeat, +Wfaces)     : faces int->float cast, 4 elems/item
//   items [.., +V)             : verts_3d, 1 vertex/item (3 floats out)
//
// Exhaustively tested in isolation, all neutral-or-worse vs this config:
// cudaMemcpyAsync path (2x slower), x2/x4 per-thread unrolls, 256-bit
// ld/st, blocked contiguous sweeps, single-wave grids, region reordering,
// streaming cache hints (__ldcs/__stcs), 512-thread blocks. Rejected on
// theory: CE+SM split and TMA bulk (shared, path-independent DRAM ceiling).
// The binding limit is DRAM mixed read/write stream efficiency.

__global__ void __launch_bounds__(256) fused_all_kernel(
    const float* __restrict__ verts_logit,
    const float* __restrict__ verts_features,
    const float* __restrict__ boundary,
    const int*   __restrict__ faces,
    float* __restrict__ out,
    int V, int faces_elems, int feat_elems,
    int feat_out_aligned)   // 1 if (3V + faces_elems) % 4 == 0
{
    const long long threeV = 3LL * V;
    float* __restrict__ out_faces    = out + threeV;
    float* __restrict__ out_features = out_faces + faces_elems;

    const int Wfeat  = feat_elems >> 2;          // feat_elems = V*128, %4 == 0
    const int Wfaces = (faces_elems + 3) >> 2;
    const int Wverts = V;
    const long long total = (long long)Wfeat + Wfaces + Wverts;

    const long long stride = (long long)gridDim.x * blockDim.x;
    for (long long idx = (long long)blockIdx.x * blockDim.x + threadIdx.x;
         idx < total; idx += stride) {
        if (idx < Wfeat) {
            // ---- bulk features copy, 16B granularity ----
            const float4 v = __ldg((const float4*)verts_features + idx);
            if (feat_out_aligned) {
                ((float4*)out_features)[idx] = v;
            } else {
                float* d = out_features + (idx << 2);
                d[0] = v.x; d[1] = v.y; d[2] = v.z; d[3] = v.w;
            }
        } else if (idx < (long long)Wfeat + Wfaces) {
            // ---- faces int32 -> float32, 4 elems/item ----
            const int j = (int)(idx - Wfeat);
            const int e = j << 2;
            if (e + 4 <= faces_elems) {
                const int4 f = __ldg((const int4*)faces + j);
                float4 o;
                o.x = (float)f.x; o.y = (float)f.y;
                o.z = (float)f.z; o.w = (float)f.w;
                ((float4*)out_faces)[j] = o;   // out_faces offset 3V %4==0
            } else {
                for (int k = e; k < faces_elems; k++)
                    out_faces[k] = (float)__ldg(faces + k);
            }
        } else {
            // ---- verts_3d: sigmoid(logit)*2-1, first 4 rows = boundary ----
            const int i = (int)(idx - Wfeat - Wfaces);
            float x, y;
            if (i < 4) {
                x = boundary[2 * i];
                y = boundary[2 * i + 1];
            } else {
                const float2 l = __ldg((const float2*)verts_logit + i);
                x = 2.0f / (1.0f + __expf(-l.x)) - 1.0f;
                y = 2.0f / (1.0f + __expf(-l.y)) - 1.0f;
            }
            float* d = out + 3LL * i;
            d[0] = x; d[1] = y; d[2] = 1.0f;
        }
    }
}

extern "C" void kernel_launch(void* const* d_in, const int* in_sizes, int n_in,
                              void* d_out, int out_size) {
    const float* verts_logit    = (const float*)d_in[0];   // V*2
    const float* verts_features = (const float*)d_in[1];   // V*D
    const float* boundary       = (const float*)d_in[2];   // 4*2
    const int*   faces          = (const int*)d_in[3];     // F*3 (int32)

    const int V           = in_sizes[0] / 2;
    const int feat_elems  = in_sizes[1];
    const int faces_elems = in_sizes[3];

    const int feat_out_aligned = (((3LL * V + faces_elems) & 3) == 0) ? 1 : 0;

    const int threads = 256;
    int blocks = 148 * 16;
    const long long total = (long long)(feat_elems >> 2)
                          + ((faces_elems + 3) >> 2) + V;
    const long long need = (total + threads - 1) / threads;
    if (need < blocks) blocks = (int)need;
    if (blocks < 1) blocks = 1;

    fused_all_kernel<<<blocks, threads>>>(
        verts_logit, verts_features, boundary, faces, (float*)d_out,
        V, faces_elems, feat_elems, feat_out_aligned);
}

// round 15
// speedup vs baseline: 1.0069x; 1.0069x over previous
#include <cuda_runtime.h>
#include <cuda_bf16.h>

// FINAL kernel — converged optimum (87.87–88.32us across 8 runs, sigma
// ~0.15us; DRAM-roofline-bound at ~6.37 TB/s combined r+w, ~80% of HBM3e
// spec for a balanced 1:1 streaming mix).
//
// Output layout (flattened f32 concat of the reference tuple):
//   [0, 3V)                      verts_3d   (V x 3)
//   [3V, 3V + Fe)                faces cast to f32 (Fe = in_sizes[3])
//   [3V + Fe, 3V + Fe + V*D)     verts_features copy
//
// One fused kernel over a flat interleaved work-item space:
//   items [0, Wfeat)           : features copy, 4 floats/item (float4)
//   items [Wfeat, +Wfaces)     : faces int->float cast, 4 elems/item
//   items [.., +V)             : verts_3d, 1 vertex/item (3 floats out)
//
// Exhaustively tested in isolation, all neutral-or-worse vs this config:
// cudaMemcpyAsync path (2x slower), x2/x4 per-thread unrolls, 256-bit
// ld/st, blocked contiguous sweeps, single-wave grids, region reordering,
// streaming cache hints (__ldcs/__stcs), 512-thread blocks. Rejected on
// theory: CE+SM split and TMA bulk (shared, path-independent DRAM ceiling).
// The binding limit is DRAM mixed read/write stream efficiency.

__global__ void __launch_bounds__(256) fused_all_kernel(
    const float* __restrict__ verts_logit,
    const float* __restrict__ verts_features,
    const float* __restrict__ boundary,
    const int*   __restrict__ faces,
    float* __restrict__ out,
    int V, int faces_elems, int feat_elems,
    int feat_out_aligned)   // 1 if (3V + faces_elems) % 4 == 0
{
    const long long threeV = 3LL * V;
    float* __restrict__ out_faces    = out + threeV;
    float* __restrict__ out_features = out_faces + faces_elems;

    const int Wfeat  = feat_elems >> 2;          // feat_elems = V*128, %4 == 0
    const int Wfaces = (faces_elems + 3) >> 2;
    const int Wverts = V;
    const long long total = (long long)Wfeat + Wfaces + Wverts;

    const long long stride = (long long)gridDim.x * blockDim.x;
    for (long long idx = (long long)blockIdx.x * blockDim.x + threadIdx.x;
         idx < total; idx += stride) {
        if (idx < Wfeat) {
            // ---- bulk features copy, 16B granularity ----
            const float4 v = __ldg((const float4*)verts_features + idx);
            if (feat_out_aligned) {
                ((float4*)out_features)[idx] = v;
            } else {
                float* d = out_features + (idx << 2);
                d[0] = v.x; d[1] = v.y; d[2] = v.z; d[3] = v.w;
            }
        } else if (idx < (long long)Wfeat + Wfaces) {
            // ---- faces int32 -> float32, 4 elems/item ----
            const int j = (int)(idx - Wfeat);
            const int e = j << 2;
            if (e + 4 <= faces_elems) {
                const int4 f = __ldg((const int4*)faces + j);
                float4 o;
                o.x = (float)f.x; o.y = (float)f.y;
                o.z = (float)f.z; o.w = (float)f.w;
                ((float4*)out_faces)[j] = o;   // out_faces offset 3V %4==0
            } else {
                for (int k = e; k < faces_elems; k++)
                    out_faces[k] = (float)__ldg(faces + k);
            }
        } else {
            // ---- verts_3d: sigmoid(logit)*2-1, first 4 rows = boundary ----
            const int i = (int)(idx - Wfeat - Wfaces);
            float x, y;
            if (i < 4) {
                x = boundary[2 * i];
                y = boundary[2 * i + 1];
            } else {
                const float2 l = __ldg((const float2*)verts_logit + i);
                x = 2.0f / (1.0f + __expf(-l.x)) - 1.0f;
                y = 2.0f / (1.0f + __expf(-l.y)) - 1.0f;
            }
            float* d = out + 3LL * i;
            d[0] = x; d[1] = y; d[2] = 1.0f;
        }
    }
}

extern "C" void kernel_launch(void* const* d_in, const int* in_sizes, int n_in,
                              void* d_out, int out_size) {
    const float* verts_logit    = (const float*)d_in[0];   // V*2
    const float* verts_features = (const float*)d_in[1];   // V*D
    const float* boundary       = (const float*)d_in[2];   // 4*2
    const int*   faces          = (const int*)d_in[3];     // F*3 (int32)

    const int V           = in_sizes[0] / 2;
    const int feat_elems  = in_sizes[1];
    const int faces_elems = in_sizes[3];

    const int feat_out_aligned = (((3LL * V + faces_elems) & 3) == 0) ? 1 : 0;

    const int threads = 256;
    int blocks = 148 * 16;
    const long long total = (long long)(feat_elems >> 2)
                          + ((faces_elems + 3) >> 2) + V;
    const long long need = (total + threads - 1) / threads;
    if (need < blocks) blocks = (int)need;
    if (blocks < 1) blocks = 1;

    fused_all_kernel<<<blocks, threads>>>(
        verts_logit, verts_features, boundary, faces, (float*)d_out,
        V, faces_elems, feat_elems, feat_out_aligned);
}